// round 8
// baseline (speedup 1.0000x reference)
#include <cuda_runtime.h>

// SSKernelDiag: K[h,l] = 2*Re( sum_n Ct[h,n] * dA[h,n]^l )
// Shapes fixed: CH=1, H=1024, N=64, L=2048.
// R4: f32x2-packed hot loop (2 n-channels per 64-bit register).

#define HH   1024
#define NN   64
#define NP   (NN / 2)     // 32 packed pairs
#define LL   2048
#define TPB  128
#define LPT  (LL / TPB)   // 16 consecutive l's per thread
#define NPOW 7            // dA^(LPT*t) via bits of t (t < 128)

typedef unsigned long long u64;

// Packed parameter tables (allocation-free: __device__ globals). ~2.4 MB.
__device__ u64 g2_Ctr[HH * NP];
__device__ u64 g2_Cti[HH * NP];
__device__ u64 g2_Ar [HH * NP];
__device__ u64 g2_Ai [HH * NP];
__device__ u64 g2_NAi[HH * NP];
__device__ u64 g2_Pr [NPOW][HH * NP];
__device__ u64 g2_Pi [NPOW][HH * NP];
__device__ u64 g2_NPi[NPOW][HH * NP];

__device__ __forceinline__ u64 pk2(float lo, float hi) {
    u64 r;
    asm("mov.b64 %0, {%1, %2};" : "=l"(r) : "f"(lo), "f"(hi));
    return r;
}
#define F2MUL(d, a, b)    asm("mul.rn.f32x2 %0, %1, %2;"     : "=l"(d) : "l"(a), "l"(b))
#define F2ADD(d, a, b)    asm("add.rn.f32x2 %0, %1, %2;"     : "=l"(d) : "l"(a), "l"(b))
#define F2FMA(d, a, b, c) asm("fma.rn.f32x2 %0, %1, %2, %3;" : "=l"(d) : "l"(a), "l"(b), "l"(c))

// ---------------------------------------------------------------------------
// Setup: one thread per packed pair (h, 2p/2p+1). 32K threads, trivial cost.
// ---------------------------------------------------------------------------
__global__ void ssd_setup_kernel(const float* __restrict__ C_ri,
                                 const float* __restrict__ log_dt,
                                 const float* __restrict__ B_ri,
                                 const float* __restrict__ invA,
                                 const float* __restrict__ Aim,
                                 int n_ssm) {
    int idx = blockIdx.x * blockDim.x + threadIdx.x;
    if (idx >= HH * NP) return;
    int h = idx / NP;
    int p = idx - h * NP;
    int tt = h % n_ssm;                // 't n -> (v t) n' tiling
    float dt = __expf(log_dt[h]);

    float ctr[2], cti[2], dar[2], dai[2];
#pragma unroll
    for (int s = 0; s < 2; s++) {
        int n  = 2 * p + s;
        int tn = tt * NN + n;
        int hn = h * NN + n;

        float Ar = -__expf(invA[tn]);
        float Ai = Aim[tn];

        float xr = 0.5f * Ar * dt;     // dtA/2
        float xi = 0.5f * Ai * dt;
        float dr = 1.0f - xr, di = -xi;   // denom = 1 - dtA/2
        float nr = 1.0f + xr, ni = xi;    // numer = 1 + dtA/2
        float inv = 1.0f / (dr * dr + di * di);

        dar[s] = (nr * dr + ni * di) * inv;
        dai[s] = (ni * dr - nr * di) * inv;

        // Ct = 2 * (B*C) * dt / denom  (factor 2 from 2*Re folded in)
        float Br = B_ri[2 * tn], Bi = B_ri[2 * tn + 1];
        float Cr = C_ri[2 * hn], Ci = C_ri[2 * hn + 1];
        float br = Br * Cr - Bi * Ci;
        float bi = Br * Ci + Bi * Cr;
        float sc = 2.0f * dt * inv;
        ctr[s] = sc * (br * dr + bi * di);
        cti[s] = sc * (bi * dr - br * di);
    }

    g2_Ctr[idx] = pk2(ctr[0], ctr[1]);
    g2_Cti[idx] = pk2(cti[0], cti[1]);
    g2_Ar [idx] = pk2(dar[0], dar[1]);
    g2_Ai [idx] = pk2(dai[0], dai[1]);
    g2_NAi[idx] = pk2(-dai[0], -dai[1]);

    // P_0 = dA^LPT (4 squarings), then P_k = P_{k-1}^2
    float pr[2] = {dar[0], dar[1]}, pi[2] = {dai[0], dai[1]};
#pragma unroll
    for (int s = 0; s < 2; s++) {
#pragma unroll
        for (int k = 0; k < 4; k++) {
            float r  = pr[s] * pr[s] - pi[s] * pi[s];
            float im = 2.0f * pr[s] * pi[s];
            pr[s] = r; pi[s] = im;
        }
    }
    g2_Pr[0][idx] = pk2(pr[0], pr[1]);
    g2_Pi[0][idx] = pk2(pi[0], pi[1]);
    g2_NPi[0][idx] = pk2(-pi[0], -pi[1]);
#pragma unroll
    for (int k = 1; k < NPOW; k++) {
#pragma unroll
        for (int s = 0; s < 2; s++) {
            float r  = pr[s] * pr[s] - pi[s] * pi[s];
            float im = 2.0f * pr[s] * pi[s];
            pr[s] = r; pi[s] = im;
        }
        g2_Pr[k][idx] = pk2(pr[0], pr[1]);
        g2_Pi[k][idx] = pk2(pi[0], pi[1]);
        g2_NPi[k][idx] = pk2(-pi[0], -pi[1]);
    }
}

// ---------------------------------------------------------------------------
// Main: one block per h. Thread t owns l in [t*LPT, t*LPT+LPT).
// f32x2-packed: each n2 iteration handles 2 channels in 64-bit registers.
// ---------------------------------------------------------------------------
__global__ void __launch_bounds__(TPB)
ssd_main_kernel(float* __restrict__ K) {
    const int h = blockIdx.x;
    const int t = threadIdx.x;
    const int base = h * NP;

    __shared__ u64 sCtr[NP], sCti[NP], sAr[NP], sAi[NP], sNAi[NP];
    __shared__ u64 sPr[NPOW][NP], sPi[NPOW][NP], sNPi[NPOW][NP];

    if (t < NP) {
        sCtr[t] = g2_Ctr[base + t];
        sCti[t] = g2_Cti[base + t];
        sAr[t]  = g2_Ar [base + t];
        sAi[t]  = g2_Ai [base + t];
        sNAi[t] = g2_NAi[base + t];
#pragma unroll
        for (int k = 0; k < NPOW; k++) {
            sPr[k][t]  = g2_Pr [k][base + t];
            sPi[k][t]  = g2_Pi [k][base + t];
            sNPi[k][t] = g2_NPi[k][base + t];
        }
    }
    __syncthreads();

    u64 acc[LPT];
    const u64 zz = 0ull;
#pragma unroll
    for (int j = 0; j < LPT; j++) acc[j] = zz;

    for (int n2 = 0; n2 < NP; n2++) {
        u64 wr = sCtr[n2], wi = sCti[n2];

        // w *= dA^(LPT*t) via squaring table (predicated, no MUFU)
#pragma unroll
        for (int k = 0; k < NPOW; k++) {
            if (t & (1 << k)) {
                u64 pr = sPr[k][n2], pi = sPi[k][n2], npi = sNPi[k][n2];
                u64 t1, t2, r, im;
                F2MUL(t1, wr, pr);
                F2FMA(r, wi, npi, t1);     // r  = wr*pr - wi*pi
                F2MUL(t2, wi, pr);
                F2FMA(im, wr, pi, t2);     // im = wr*pi + wi*pr
                wr = r; wi = im;
            }
        }

        const u64 ar = sAr[n2], ai = sAi[n2], nai = sNAi[n2];

        // 16 geometric steps: acc[j] += Re(w) (packed); w *= dA
#pragma unroll
        for (int j = 0; j < LPT; j++) {
            F2ADD(acc[j], acc[j], wr);
            u64 t1, t2, r, im;
            F2MUL(t1, wr, ar);
            F2FMA(r, wi, nai, t1);
            F2MUL(t2, wi, ar);
            F2FMA(im, wr, ai, t2);
            wr = r; wi = im;
        }
    }

    // Horizontal add of the two packed lanes; 4x STG.128
    float res[LPT];
#pragma unroll
    for (int j = 0; j < LPT; j++) {
        float lo, hi;
        asm("mov.b64 {%0, %1}, %2;" : "=f"(lo), "=f"(hi) : "l"(acc[j]));
        res[j] = lo + hi;
    }
    float4* out = reinterpret_cast<float4*>(K + h * LL + t * LPT);
#pragma unroll
    for (int j = 0; j < LPT / 4; j++) {
        out[j] = make_float4(res[4 * j], res[4 * j + 1],
                             res[4 * j + 2], res[4 * j + 3]);
    }
}

// ---------------------------------------------------------------------------
extern "C" void kernel_launch(void* const* d_in, const int* in_sizes, int n_in,
                              void* d_out, int out_size) {
    const float* C_ri   = (const float*)d_in[0];
    const float* log_dt = (const float*)d_in[1];
    const float* B_ri   = (const float*)d_in[2];
    const float* invA   = (const float*)d_in[3];
    const float* Aim    = (const float*)d_in[4];

    int n_ssm = in_sizes[3] / NN;   // inv_A_real is (n_ssm, N)
    if (n_ssm <= 0) n_ssm = HH;

    ssd_setup_kernel<<<(HH * NP + 255) / 256, 256>>>(C_ri, log_dt, B_ri,
                                                     invA, Aim, n_ssm);
    ssd_main_kernel<<<HH, TPB>>>((float*)d_out);
}